// round 13
// baseline (speedup 1.0000x reference)
#include <cuda_runtime.h>

#define NBINS 28
#define HID   16
#define FEAT  8
#define TPB   128   // threads per block
#define EPT   3     // elements per thread (weight-load amortization)

typedef unsigned long long u64;

// Cross-block bin accumulator + ticket. Zero-initialized at module load.
// Protocol: every launch leaves g_bins at zero (last block drains via
// atomicExch) and only ever uses g_ticket modulo gridDim -> replay-safe.
__device__ float    g_bins[NBINS];
__device__ unsigned g_ticket;

__device__ __forceinline__ float sigmoid_exact(float v) {
    return 1.0f / (1.0f + __expf(-v));
}
__device__ __forceinline__ u64 pack2(float lo, float hi) {
    u64 r; asm("mov.b64 %0, {%1, %2};" : "=l"(r) : "f"(lo), "f"(hi)); return r;
}
__device__ __forceinline__ void unpack2(u64 v, float& lo, float& hi) {
    asm("mov.b64 {%0, %1}, %2;" : "=f"(lo), "=f"(hi) : "l"(v));
}
__device__ __forceinline__ u64 fma2(u64 a, u64 b, u64 c) {
    u64 d; asm("fma.rn.f32x2 %0, %1, %2, %3;" : "=l"(d) : "l"(a), "l"(b), "l"(c)); return d;
}
__device__ __forceinline__ float tanh_fast(float x) {
    float y; asm("tanh.approx.f32 %0, %1;" : "=f"(y) : "f"(x)); return y;
}

// ---------------------------------------------------------------------------
// Single fused kernel.
//   - per-element LDGs hoisted to the top (latency hidden behind staging)
//   - threads 0..39 compute the exact ml-MLP table (stab[1..40]) in the
//     staging phase (each block redundantly; ~300 FMAs, hidden)
//   - tanh-folded mh MLP, packed fma.rn.f32x2, EPT=3
//   - bins: shared privatization -> global g_bins atomics -> last block
//     (ticket) drains g_bins with atomicExch and writes out_bins = sum + base
// ---------------------------------------------------------------------------
__global__ __launch_bounds__(TPB, 4)
void dnn_fused_kernel(
    const float* __restrict__ x_feat,
    const float* __restrict__ W1, const float* __restrict__ b1,
    const float* __restrict__ W2, const float* __restrict__ b2,
    const float* __restrict__ W3, const float* __restrict__ b3,
    const float* __restrict__ mlW1, const float* __restrict__ mlb1,
    const float* __restrict__ mlW2, const float* __restrict__ mlb2,
    const float* __restrict__ mlW3, const float* __restrict__ mlb3,
    const int*   __restrict__ del_lens,
    const int*   __restrict__ mh_len,
    float* __restrict__ out,
    float* __restrict__ out_bins,
    int n)
{
    __shared__ __align__(16) float sA1[FEAT * HID];   // W1 * 0.5
    __shared__ __align__(16) float sC1[HID];          // b1 * 0.5
    __shared__ __align__(16) float sA2[HID * HID];    // W2 * 0.25
    __shared__ __align__(16) float sC2[HID];          // b2*0.5 + colsum(W2)*0.25
    __shared__ __align__(16) float sA3[HID];          // W3 * 0.5
    __shared__ float sC3;                             // b3 + sum(W3)*0.5
    __shared__ float stab[41];                        // mhless table, dl=1..40
    __shared__ float sbins[NBINS];
    __shared__ int   s_last;

    const int tid = threadIdx.x;

    // ---- per-element global loads FIRST ----
    int  gi[EPT];
    bool vv[EPT];
    #pragma unroll
    for (int e = 0; e < EPT; e++) {
        gi[e] = blockIdx.x * (TPB * EPT) + e * TPB + tid;
        vv[e] = (gi[e] < n);
    }
    float x[EPT][FEAT];
    int   dreg[EPT], mreg[EPT];
    #pragma unroll
    for (int e = 0; e < EPT; e++) {
        int j = vv[e] ? gi[e] : 0;
        float4 a = *reinterpret_cast<const float4*>(x_feat + (size_t)j * FEAT);
        float4 c = *reinterpret_cast<const float4*>(x_feat + (size_t)j * FEAT + 4);
        x[e][0]=a.x; x[e][1]=a.y; x[e][2]=a.z; x[e][3]=a.w;
        x[e][4]=c.x; x[e][5]=c.y; x[e][6]=c.z; x[e][7]=c.w;
        dreg[e] = del_lens[j];
        mreg[e] = mh_len[j];
    }

    // ---- weight staging ----
    for (int i = tid; i < FEAT * HID; i += TPB) sA1[i] = 0.5f * W1[i];
    for (int i = tid; i < HID * HID; i += TPB) sA2[i] = 0.25f * W2[i];
    if (tid < HID) {
        sC1[tid] = 0.5f * b1[tid];
        float s = 0.0f;
        #pragma unroll
        for (int i = 0; i < HID; i++) s += W2[i * HID + tid];
        sC2[tid] = fmaf(0.25f, s, 0.5f * b2[tid]);
        sA3[tid] = 0.5f * W3[tid];
    }
    if (tid == 32) {
        float s = 0.0f;
        #pragma unroll
        for (int i = 0; i < HID; i++) s += W3[i];
        sC3 = fmaf(0.5f, s, b3[0]);
    }
    if (tid >= 96 && tid < 96 + NBINS) sbins[tid - 96] = 0.0f;

    // ---- ml-MLP table (threads 64..103 -> dl = 1..40), exact sigmoid ----
    if (tid >= 64 && tid < 64 + 40) {
        float dl = (float)(tid - 64 + 1);
        float h1[HID];
        #pragma unroll
        for (int o = 0; o < HID; o++)
            h1[o] = sigmoid_exact(fmaf(dl, mlW1[o], mlb1[o]));
        float h2[HID];
        #pragma unroll
        for (int o = 0; o < HID; o++) {
            float a = mlb2[o];
            #pragma unroll
            for (int i = 0; i < HID; i++)
                a = fmaf(h1[i], mlW2[i * HID + o], a);
            h2[o] = sigmoid_exact(a);
        }
        float phi = mlb3[0];
        #pragma unroll
        for (int i = 0; i < HID; i++)
            phi = fmaf(h2[i], mlW3[i], phi);
        stab[tid - 64 + 1] = __expf(phi - 0.25f * dl);
    }
    __syncthreads();

    // ---- layer 1 ----
    u64 z1[EPT][8];
    {
        const ulonglong2* cp = reinterpret_cast<const ulonglong2*>(sC1);
        ulonglong2 c0 = cp[0], c1v = cp[1], c2v = cp[2], c3v = cp[3];
        #pragma unroll
        for (int e = 0; e < EPT; e++) {
            z1[e][0]=c0.x;  z1[e][1]=c0.y;  z1[e][2]=c1v.x; z1[e][3]=c1v.y;
            z1[e][4]=c2v.x; z1[e][5]=c2v.y; z1[e][6]=c3v.x; z1[e][7]=c3v.y;
        }
    }
    #pragma unroll
    for (int i = 0; i < FEAT; i++) {
        const ulonglong2* w = reinterpret_cast<const ulonglong2*>(sA1 + i * HID);
        ulonglong2 wa = w[0], wb = w[1], wc = w[2], wd = w[3];
        #pragma unroll
        for (int e = 0; e < EPT; e++) {
            u64 p = pack2(x[e][i], x[e][i]);
            z1[e][0]=fma2(p,wa.x,z1[e][0]); z1[e][1]=fma2(p,wa.y,z1[e][1]);
            z1[e][2]=fma2(p,wb.x,z1[e][2]); z1[e][3]=fma2(p,wb.y,z1[e][3]);
            z1[e][4]=fma2(p,wc.x,z1[e][4]); z1[e][5]=fma2(p,wc.y,z1[e][5]);
            z1[e][6]=fma2(p,wd.x,z1[e][6]); z1[e][7]=fma2(p,wd.y,z1[e][7]);
        }
    }

    // ---- tanh ----
    float t1[EPT][HID];
    #pragma unroll
    for (int e = 0; e < EPT; e++)
        #pragma unroll
        for (int o = 0; o < 8; o++) {
            float lo, hi; unpack2(z1[e][o], lo, hi);
            t1[e][2*o] = tanh_fast(lo); t1[e][2*o+1] = tanh_fast(hi);
        }

    // ---- layer 2 ----
    u64 z2[EPT][8];
    {
        const ulonglong2* cp = reinterpret_cast<const ulonglong2*>(sC2);
        ulonglong2 c0 = cp[0], c1v = cp[1], c2v = cp[2], c3v = cp[3];
        #pragma unroll
        for (int e = 0; e < EPT; e++) {
            z2[e][0]=c0.x;  z2[e][1]=c0.y;  z2[e][2]=c1v.x; z2[e][3]=c1v.y;
            z2[e][4]=c2v.x; z2[e][5]=c2v.y; z2[e][6]=c3v.x; z2[e][7]=c3v.y;
        }
    }
    #pragma unroll
    for (int i = 0; i < HID; i++) {
        const ulonglong2* w = reinterpret_cast<const ulonglong2*>(sA2 + i * HID);
        ulonglong2 wa = w[0], wb = w[1], wc = w[2], wd = w[3];
        #pragma unroll
        for (int e = 0; e < EPT; e++) {
            u64 p = pack2(t1[e][i], t1[e][i]);
            z2[e][0]=fma2(p,wa.x,z2[e][0]); z2[e][1]=fma2(p,wa.y,z2[e][1]);
            z2[e][2]=fma2(p,wb.x,z2[e][2]); z2[e][3]=fma2(p,wb.y,z2[e][3]);
            z2[e][4]=fma2(p,wc.x,z2[e][4]); z2[e][5]=fma2(p,wc.y,z2[e][5]);
            z2[e][6]=fma2(p,wd.x,z2[e][6]); z2[e][7]=fma2(p,wd.y,z2[e][7]);
        }
    }

    // ---- tanh + layer 3 ----
    float phi[EPT];
    #pragma unroll
    for (int e = 0; e < EPT; e++) phi[e] = sC3;
    #pragma unroll
    for (int o = 0; o < 8; o++) {
        float w0 = sA3[2*o], w1 = sA3[2*o+1];
        #pragma unroll
        for (int e = 0; e < EPT; e++) {
            float lo, hi; unpack2(z2[e][o], lo, hi);
            phi[e] = fmaf(tanh_fast(lo), w0, phi[e]);
            phi[e] = fmaf(tanh_fast(hi), w1, phi[e]);
        }
    }

    // ---- epilogue ----
    #pragma unroll
    for (int e = 0; e < EPT; e++) {
        if (vv[e]) {
            int d  = dreg[e];
            int mh = mreg[e];
            float score = __expf(fmaf(-0.25f, (float)d, phi[e]));
            float contrib = 0.0f;
            if (d == mh && d <= 40) contrib = stab[d];
            out[gi[e]] = score + contrib;
            if (d <= NBINS) atomicAdd(&sbins[d - 1], score);
        }
    }

    __syncthreads();

    // ---- flush block bins to global accumulator ----
    if (tid < NBINS) {
        float v = sbins[tid];
        if (v != 0.0f) atomicAdd(&g_bins[tid], v);
    }
    __threadfence();   // make this block's adds visible before ticket
    __syncthreads();

    if (tid == 0) {
        unsigned old = atomicAdd(&g_ticket, 1u);
        s_last = ((old % gridDim.x) == gridDim.x - 1u) ? 1 : 0;
    }
    __syncthreads();

    // ---- last block: drain + reset g_bins, write out_bins with baseline ----
    if (s_last && tid < NBINS) {
        float acc = atomicExch(&g_bins[tid], 0.0f);   // read all adds + reset
        out_bins[tid] = acc + stab[tid + 1];          // + dl2_scores baseline
    }
}

// ---------------------------------------------------------------------------
// Launch
// ---------------------------------------------------------------------------
extern "C" void kernel_launch(void* const* d_in, const int* in_sizes, int n_in,
                              void* d_out, int out_size)
{
    const float* x_feat = (const float*)d_in[0];
    const float* mh_W1  = (const float*)d_in[1];
    const float* mh_b1  = (const float*)d_in[2];
    const float* mh_W2  = (const float*)d_in[3];
    const float* mh_b2  = (const float*)d_in[4];
    const float* mh_W3  = (const float*)d_in[5];
    const float* mh_b3  = (const float*)d_in[6];
    const float* ml_W1  = (const float*)d_in[7];
    const float* ml_b1  = (const float*)d_in[8];
    const float* ml_W2  = (const float*)d_in[9];
    const float* ml_b2  = (const float*)d_in[10];
    const float* ml_W3  = (const float*)d_in[11];
    const float* ml_b3  = (const float*)d_in[12];
    const int*   del_lens = (const int*)d_in[13];
    const int*   mh_len   = (const int*)d_in[14];

    int n = in_sizes[13];
    float* out      = (float*)d_out;
    float* out_bins = out + n;

    int blocks = (n + TPB * EPT - 1) / (TPB * EPT);
    dnn_fused_kernel<<<blocks, TPB>>>(x_feat,
                                      mh_W1, mh_b1, mh_W2, mh_b2, mh_W3, mh_b3,
                                      ml_W1, ml_b1, ml_W2, ml_b2, ml_W3, ml_b3,
                                      del_lens, mh_len,
                                      out, out_bins, n);
}

// round 14
// speedup vs baseline: 3.4854x; 3.4854x over previous
#include <cuda_runtime.h>

#define NBINS 28
#define HID   16
#define FEAT  8
#define TPB   128   // threads per block
#define EPT   3     // elements per thread (weight-load amortization)

typedef unsigned long long u64;

// mhless table: t[dl] = exp(ml_mlp(dl) - 0.25*dl) for dl = 1..40
__device__ float g_mhless[41];

__device__ __forceinline__ float sigmoid_exact(float v) {
    return 1.0f / (1.0f + __expf(-v));
}
__device__ __forceinline__ u64 pack2(float lo, float hi) {
    u64 r; asm("mov.b64 %0, {%1, %2};" : "=l"(r) : "f"(lo), "f"(hi)); return r;
}
__device__ __forceinline__ void unpack2(u64 v, float& lo, float& hi) {
    asm("mov.b64 {%0, %1}, %2;" : "=f"(lo), "=f"(hi) : "l"(v));
}
__device__ __forceinline__ u64 fma2(u64 a, u64 b, u64 c) {
    u64 d; asm("fma.rn.f32x2 %0, %1, %2, %3;" : "=l"(d) : "l"(a), "l"(b), "l"(c)); return d;
}
__device__ __forceinline__ float tanh_fast(float x) {
    float y; asm("tanh.approx.f32 %0, %1;" : "=f"(y) : "f"(x)); return y;
}

// ---------------------------------------------------------------------------
// Init kernel (separate launch — R13 proved per-block fusion is poison):
// exact ml-MLP table for dl = 1..40; writes dl2_scores baseline into out_bins.
// ---------------------------------------------------------------------------
__global__ void dnn_init_kernel(
    const float* __restrict__ ml_W1, const float* __restrict__ ml_b1,
    const float* __restrict__ ml_W2, const float* __restrict__ ml_b2,
    const float* __restrict__ ml_W3, const float* __restrict__ ml_b3,
    float* __restrict__ out_bins)
{
    int t = threadIdx.x;
    if (t >= 40) return;
    float dl = (float)(t + 1);

    float h1[HID];
    #pragma unroll
    for (int o = 0; o < HID; o++)
        h1[o] = sigmoid_exact(fmaf(dl, ml_W1[o], ml_b1[o]));

    float h2[HID];
    #pragma unroll
    for (int o = 0; o < HID; o++) {
        float a = ml_b2[o];
        #pragma unroll
        for (int i = 0; i < HID; i++)
            a = fmaf(h1[i], ml_W2[i * HID + o], a);
        h2[o] = sigmoid_exact(a);
    }

    float phi = ml_b3[0];
    #pragma unroll
    for (int i = 0; i < HID; i++)
        phi = fmaf(h2[i], ml_W3[i], phi);

    float v = __expf(phi - 0.25f * dl);
    g_mhless[t + 1] = v;
    if (t < NBINS) out_bins[t] = v;
}

// ---------------------------------------------------------------------------
// Main kernel. Tanh-folded MLP, packed fma.rn.f32x2, EPT=3, hoisted LDGs.
// Layers split into TWO OUTPUT-HALVES (4 u64 accumulators live at a time)
// to cut peak registers -> 5 blocks/SM.
// ---------------------------------------------------------------------------
__global__ __launch_bounds__(TPB, 5)
void dnn_main_kernel(
    const float* __restrict__ x_feat,
    const float* __restrict__ W1, const float* __restrict__ b1,
    const float* __restrict__ W2, const float* __restrict__ b2,
    const float* __restrict__ W3, const float* __restrict__ b3,
    const int*   __restrict__ del_lens,
    const int*   __restrict__ mh_len,
    float* __restrict__ out,
    float* __restrict__ out_bins,
    int n)
{
    __shared__ __align__(16) float sA1[FEAT * HID];   // W1 * 0.5
    __shared__ __align__(16) float sC1[HID];          // b1 * 0.5
    __shared__ __align__(16) float sA2[HID * HID];    // W2 * 0.25
    __shared__ __align__(16) float sC2[HID];          // b2*0.5 + colsum(W2)*0.25
    __shared__ __align__(16) float sA3[HID];          // W3 * 0.5
    __shared__ float sC3;                             // b3 + sum(W3)*0.5
    __shared__ float stab[41];
    __shared__ float sbins[NBINS];

    const int tid = threadIdx.x;

    // ---- per-element global loads FIRST (latency hidden behind staging) ----
    int  gi[EPT];
    bool vv[EPT];
    #pragma unroll
    for (int e = 0; e < EPT; e++) {
        gi[e] = blockIdx.x * (TPB * EPT) + e * TPB + tid;
        vv[e] = (gi[e] < n);
    }
    float x[EPT][FEAT];
    int   dreg[EPT], mreg[EPT];
    #pragma unroll
    for (int e = 0; e < EPT; e++) {
        int j = vv[e] ? gi[e] : 0;
        float4 a = *reinterpret_cast<const float4*>(x_feat + (size_t)j * FEAT);
        float4 c = *reinterpret_cast<const float4*>(x_feat + (size_t)j * FEAT + 4);
        x[e][0]=a.x; x[e][1]=a.y; x[e][2]=a.z; x[e][3]=a.w;
        x[e][4]=c.x; x[e][5]=c.y; x[e][6]=c.z; x[e][7]=c.w;
        dreg[e] = del_lens[j];
        mreg[e] = mh_len[j];
    }

    // ---- weight staging ----
    for (int i = tid; i < FEAT * HID; i += TPB) sA1[i] = 0.5f * W1[i];
    for (int i = tid; i < HID * HID; i += TPB) sA2[i] = 0.25f * W2[i];
    if (tid < HID) {
        sC1[tid] = 0.5f * b1[tid];
        float s = 0.0f;
        #pragma unroll
        for (int i = 0; i < HID; i++) s += W2[i * HID + tid];
        sC2[tid] = fmaf(0.25f, s, 0.5f * b2[tid]);
        sA3[tid] = 0.5f * W3[tid];
    }
    if (tid == 32) {
        float s = 0.0f;
        #pragma unroll
        for (int i = 0; i < HID; i++) s += W3[i];
        sC3 = fmaf(0.5f, s, b3[0]);
    }
    if (tid >= 64 && tid < 64 + 41) stab[tid - 64] = g_mhless[tid - 64];
    if (tid >= 96 && tid < 96 + NBINS) sbins[tid - 96] = 0.0f;
    __syncthreads();

    // ---- layer 1 in two output-halves (4 u64 accumulators live) ----
    float t1[EPT][HID];
    #pragma unroll
    for (int h = 0; h < 2; h++) {
        u64 z[EPT][4];
        {
            const ulonglong2* cp = reinterpret_cast<const ulonglong2*>(sC1 + h * 8);
            ulonglong2 c0 = cp[0], c1v = cp[1];
            #pragma unroll
            for (int e = 0; e < EPT; e++) {
                z[e][0]=c0.x; z[e][1]=c0.y; z[e][2]=c1v.x; z[e][3]=c1v.y;
            }
        }
        #pragma unroll
        for (int i = 0; i < FEAT; i++) {
            const ulonglong2* w = reinterpret_cast<const ulonglong2*>(sA1 + i * HID + h * 8);
            ulonglong2 wa = w[0], wb = w[1];
            #pragma unroll
            for (int e = 0; e < EPT; e++) {
                u64 p = pack2(x[e][i], x[e][i]);
                z[e][0]=fma2(p,wa.x,z[e][0]); z[e][1]=fma2(p,wa.y,z[e][1]);
                z[e][2]=fma2(p,wb.x,z[e][2]); z[e][3]=fma2(p,wb.y,z[e][3]);
            }
        }
        #pragma unroll
        for (int e = 0; e < EPT; e++)
            #pragma unroll
            for (int o = 0; o < 4; o++) {
                float lo, hi; unpack2(z[e][o], lo, hi);
                t1[e][h*8 + 2*o]     = tanh_fast(lo);
                t1[e][h*8 + 2*o + 1] = tanh_fast(hi);
            }
    }

    // ---- layer 2 + layer 3, two output-halves; z2 half dies immediately ----
    float phi[EPT];
    #pragma unroll
    for (int e = 0; e < EPT; e++) phi[e] = sC3;

    #pragma unroll
    for (int h = 0; h < 2; h++) {
        u64 z[EPT][4];
        {
            const ulonglong2* cp = reinterpret_cast<const ulonglong2*>(sC2 + h * 8);
            ulonglong2 c0 = cp[0], c1v = cp[1];
            #pragma unroll
            for (int e = 0; e < EPT; e++) {
                z[e][0]=c0.x; z[e][1]=c0.y; z[e][2]=c1v.x; z[e][3]=c1v.y;
            }
        }
        #pragma unroll
        for (int i = 0; i < HID; i++) {
            const ulonglong2* w = reinterpret_cast<const ulonglong2*>(sA2 + i * HID + h * 8);
            ulonglong2 wa = w[0], wb = w[1];
            #pragma unroll
            for (int e = 0; e < EPT; e++) {
                u64 p = pack2(t1[e][i], t1[e][i]);
                z[e][0]=fma2(p,wa.x,z[e][0]); z[e][1]=fma2(p,wa.y,z[e][1]);
                z[e][2]=fma2(p,wb.x,z[e][2]); z[e][3]=fma2(p,wb.y,z[e][3]);
            }
        }
        #pragma unroll
        for (int o = 0; o < 4; o++) {
            float w0 = sA3[h*8 + 2*o], w1 = sA3[h*8 + 2*o + 1];
            #pragma unroll
            for (int e = 0; e < EPT; e++) {
                float lo, hi; unpack2(z[e][o], lo, hi);
                phi[e] = fmaf(tanh_fast(lo), w0, phi[e]);
                phi[e] = fmaf(tanh_fast(hi), w1, phi[e]);
            }
        }
    }

    // ---- epilogue (d/mh already in regs) ----
    #pragma unroll
    for (int e = 0; e < EPT; e++) {
        if (vv[e]) {
            int d  = dreg[e];
            int mh = mreg[e];
            float score = __expf(fmaf(-0.25f, (float)d, phi[e]));
            float contrib = 0.0f;
            if (d == mh && d <= 40) contrib = stab[d];
            out[gi[e]] = score + contrib;
            if (d <= NBINS) atomicAdd(&sbins[d - 1], score);
        }
    }

    __syncthreads();
    if (tid < NBINS) {
        float v = sbins[tid];
        if (v != 0.0f) atomicAdd(&out_bins[tid], v);
    }
}

// ---------------------------------------------------------------------------
// Launch
// ---------------------------------------------------------------------------
extern "C" void kernel_launch(void* const* d_in, const int* in_sizes, int n_in,
                              void* d_out, int out_size)
{
    const float* x_feat = (const float*)d_in[0];
    const float* mh_W1  = (const float*)d_in[1];
    const float* mh_b1  = (const float*)d_in[2];
    const float* mh_W2  = (const float*)d_in[3];
    const float* mh_b2  = (const float*)d_in[4];
    const float* mh_W3  = (const float*)d_in[5];
    const float* mh_b3  = (const float*)d_in[6];
    const float* ml_W1  = (const float*)d_in[7];
    const float* ml_b1  = (const float*)d_in[8];
    const float* ml_W2  = (const float*)d_in[9];
    const float* ml_b2  = (const float*)d_in[10];
    const float* ml_W3  = (const float*)d_in[11];
    const float* ml_b3  = (const float*)d_in[12];
    const int*   del_lens = (const int*)d_in[13];
    const int*   mh_len   = (const int*)d_in[14];

    int n = in_sizes[13];
    float* out      = (float*)d_out;
    float* out_bins = out + n;

    dnn_init_kernel<<<1, 64>>>(ml_W1, ml_b1, ml_W2, ml_b2, ml_W3, ml_b3, out_bins);

    int blocks = (n + TPB * EPT - 1) / (TPB * EPT);
    dnn_main_kernel<<<blocks, TPB>>>(x_feat,
                                     mh_W1, mh_b1, mh_W2, mh_b2, mh_W3, mh_b3,
                                     del_lens, mh_len,
                                     out, out_bins, n);
}